// round 10
// baseline (speedup 1.0000x reference)
#include <cuda_runtime.h>
#include <cstdint>

// SigmaModel, persistent-CTA, 1024 threads, dup-H + pipelined 8-row epilogue.
// h = relu([s,a] @ W1^T + b1); tri = h @ W2^T + b2;
// out[b,i,j] = tri[t(min(i,j),max(i,j))], diag -> exp.
// Thread tile 2r x 18c (all f32x2 pairs); H stored duplicated so GEMM loads
// (h,h) directly via LDS.64; H region aliased by double-buffered tri chunks.

#define BATCH    131072
#define SDIM     32
#define ADIM     8
#define INDIM    40
#define HID      64
#define TRI      528
#define ROWS     64               // rows per tile
#define NT       1024
#define GRID     152              // GB300 SM count
#define NTILES   (BATCH / ROWS)   // 2048
#define NPAD     580              // W2 k-major stride (mult of 4)
#define TPAD     578              // tri chunk stride (u64-aligned rows)
#define HPAD     132              // dup-H stride: mult of 4; mod32=4 -> banked rows
#define XPAD     40               // X stride (16B-aligned cp.async rows)

// shared memory layout (float offsets)
#define SM_W2    0                // [64][NPAD] = 37120, persists
#define SM_SHR   37120            // 9248: dup-H [64][HPAD]=8448  /  tri 2 x [8][TPAD]=9248
#define SM_X     46368            // [64][XPAD] = 2560
#define SM_W1    48928            // [40][64] transposed = 2560
#define SM_B1    51488            // [64]
#define SM_B2    51552            // [576]
#define SM_TBL   52128            // int[1024]
#define SM_FLOATS 53152           // 212608 bytes

#define TRIBUF   4624             // floats per tri buffer (8*TPAD)

typedef unsigned long long u64;

__device__ __forceinline__ u64 pack2(float lo, float hi) {
    u64 r; asm("mov.b64 %0, {%1, %2};" : "=l"(r) : "f"(lo), "f"(hi)); return r;
}
__device__ __forceinline__ void unpack2(u64 v, float& lo, float& hi) {
    asm("mov.b64 {%0, %1}, %2;" : "=f"(lo), "=f"(hi) : "l"(v));
}
__device__ __forceinline__ void fma2(u64& d, u64 a, u64 b) {
    asm("fma.rn.f32x2 %0, %1, %2, %0;" : "+l"(d) : "l"(a), "l"(b));
}
__device__ __forceinline__ uint32_t smem_u32(const void* p) {
    uint32_t r;
    asm("{ .reg .u64 t; cvta.to.shared.u64 t, %1; cvt.u32.u64 %0, t; }" : "=r"(r) : "l"(p));
    return r;
}
__device__ __forceinline__ void cp16(uint32_t dst, const void* src) {
    asm volatile("cp.async.ca.shared.global [%0], [%1], 16;" :: "r"(dst), "l"(src));
}
__device__ __forceinline__ void cp_commit() {
    asm volatile("cp.async.commit_group;" ::: "memory");
}
__device__ __forceinline__ void cp_wait0() {
    asm volatile("cp.async.wait_group 0;" ::: "memory");
}

__global__ void __launch_bounds__(NT, 1)
sigma_persist_kernel(const float* __restrict__ s,
                     const float* __restrict__ a,
                     const float* __restrict__ W1,
                     const float* __restrict__ b1,
                     const float* __restrict__ W2,
                     const float* __restrict__ b2,
                     float* __restrict__ out) {
    extern __shared__ float smem[];
    float* sW2  = smem + SM_W2;
    float* sSHR = smem + SM_SHR;   // dup-H, later tri chunks
    float* sX   = smem + SM_X;
    float* sW1  = smem + SM_W1;
    float* sB1  = smem + SM_B1;
    float* sB2  = smem + SM_B2;
    int*   sTbl = (int*)(smem + SM_TBL);

    const int tid = threadIdx.x;
    const uint32_t sXaddr = smem_u32(sX);

    // ================= one-time staging =================
    // W2[t][k] -> sW2[k][t] via LDG.128 along k
    for (int idx = tid; idx < TRI * (HID / 4); idx += NT) {
        int t = idx >> 4, k4 = idx & 15;
        float4 w = *reinterpret_cast<const float4*>(&W2[t * HID + k4 * 4]);
        sW2[(4 * k4 + 0) * NPAD + t] = w.x;
        sW2[(4 * k4 + 1) * NPAD + t] = w.y;
        sW2[(4 * k4 + 2) * NPAD + t] = w.z;
        sW2[(4 * k4 + 3) * NPAD + t] = w.w;
    }
    // zero-pad W2 cols [TRI, NPAD)
    for (int idx = tid; idx < HID * (NPAD - TRI); idx += NT) {
        int k = idx / (NPAD - TRI), t = TRI + (idx - k * (NPAD - TRI));
        sW2[k * NPAD + t] = 0.0f;
    }
    // W1[hh][k] -> sW1[k][hh]
    for (int idx = tid; idx < HID * INDIM; idx += NT) {
        int hh = idx / INDIM, k = idx - hh * INDIM;
        sW1[k * HID + hh] = W1[idx];
    }
    if (tid < HID) sB1[tid] = b1[tid];
    for (int idx = tid; idx < 576; idx += NT)
        sB2[idx] = (idx < TRI) ? b2[idx] : 0.0f;
    // scatter table: out (i,j) -> tri index | diag flag
    for (int o = tid; o < 1024; o += NT) {
        int i = o >> 5, j = o & 31;
        int ii = (i < j) ? i : j;
        int jj = (i < j) ? j : i;
        int t = ii * 32 - ((ii * (ii + 1)) >> 1) + jj;
        sTbl[o] = t | ((i == j) ? (1 << 16) : 0);
    }

    // prefetch X for first tile
    const int tile0 = blockIdx.x;
    {
        int row0 = tile0 * ROWS;
        if (tid < 512) {
            int r = tid >> 3, c4 = tid & 7;
            cp16(sXaddr + (r * XPAD + c4 * 4) * 4, &s[(size_t)(row0 + r) * SDIM + c4 * 4]);
        } else if (tid < 640) {
            int t2 = tid - 512, r2 = t2 >> 1, d4 = t2 & 1;
            cp16(sXaddr + (r2 * XPAD + SDIM + d4 * 4) * 4,
                 &a[(size_t)(row0 + r2) * ADIM + d4 * 4]);
        }
        cp_commit();
    }
    cp_wait0();
    __syncthreads();

    // GEMM mapping: 32 warps = 4 row-blocks(16r) x 8 col-blocks(72c).
    // Lane: rg = lane&7 (rows rg + 8m, m<2), cg = lane>>3 (18 cols = 9 pairs).
    const int wi   = tid >> 5, lane = tid & 31;
    const int rb   = wi >> 3,  cb   = wi & 7;
    const int rg   = lane & 7, cg   = lane >> 3;
    const int wcol = cb * 72;
    const int4* tbl4 = reinterpret_cast<const int4*>(sTbl);

    // ================= persistent tile loop =================
    for (int tile = tile0; tile < NTILES; tile += GRID) {
        const int row0 = tile * ROWS;

        // ---- Phase 1: H = relu(X @ W1^T + b1), stored DUPLICATED ----
        {
            const int r  = tid >> 4;           // 0..63
            const int hg = (tid & 15) * 4;     // 4 hidden cols = 2 pairs
            u64 acc[2];
            acc[0] = *reinterpret_cast<const u64*>(&sB1[hg]);
            acc[1] = *reinterpret_cast<const u64*>(&sB1[hg + 2]);
            const float* xrow = &sX[r * XPAD];
#pragma unroll 5
            for (int k = 0; k < INDIM; ++k) {
                u64 xb = pack2(xrow[k], xrow[k]);
                const ulonglong2 w = *reinterpret_cast<const ulonglong2*>(&sW1[k * HID + hg]);
                fma2(acc[0], xb, w.x);
                fma2(acc[1], xb, w.y);
            }
            float l0, h0, l1, h1;
            unpack2(acc[0], l0, h0);
            unpack2(acc[1], l1, h1);
            l0 = fmaxf(l0, 0.f); h0 = fmaxf(h0, 0.f);
            l1 = fmaxf(l1, 0.f); h1 = fmaxf(h1, 0.f);
            float* hrow = &sSHR[r * HPAD + 2 * hg];
            *reinterpret_cast<float4*>(hrow)     = make_float4(l0, l0, h0, h0);
            *reinterpret_cast<float4*>(hrow + 4) = make_float4(l1, l1, h1, h1);
        }
        __syncthreads();   // dup-H ready; sX free for prefetch

        // ---- Phase 2: tri = H @ W2^T + b2 (thread tile 2r x 18c, all pairs) ----
        u64 acc2[2][9];
#pragma unroll
        for (int q = 0; q < 4; ++q) {
            u64 blo = *reinterpret_cast<const u64*>(&sB2[wcol + 16 * q + 4 * cg]);
            u64 bhi = *reinterpret_cast<const u64*>(&sB2[wcol + 16 * q + 4 * cg + 2]);
            acc2[0][2 * q] = blo; acc2[0][2 * q + 1] = bhi;
            acc2[1][2 * q] = blo; acc2[1][2 * q + 1] = bhi;
        }
        {
            u64 bt = *reinterpret_cast<const u64*>(&sB2[wcol + 64 + 2 * cg]);
            acc2[0][8] = bt; acc2[1][8] = bt;
        }

        const float* hbase = &sSHR[(rb * 16 + rg) * HPAD];
#pragma unroll 4
        for (int k = 0; k < HID; ++k) {
            const u64 hb0 = *reinterpret_cast<const u64*>(hbase + 2 * k);              // (h,h)
            const u64 hb1 = *reinterpret_cast<const u64*>(hbase + 8 * HPAD + 2 * k);
            const float* wr = &sW2[k * NPAD + wcol];
#pragma unroll
            for (int q = 0; q < 4; ++q) {
                const ulonglong2 w = *reinterpret_cast<const ulonglong2*>(wr + 16 * q + 4 * cg);
                fma2(acc2[0][2 * q],     hb0, w.x);
                fma2(acc2[0][2 * q + 1], hb0, w.y);
                fma2(acc2[1][2 * q],     hb1, w.x);
                fma2(acc2[1][2 * q + 1], hb1, w.y);
            }
            {
                const u64 wt = *reinterpret_cast<const u64*>(wr + 64 + 2 * cg);
                fma2(acc2[0][8], hb0, wt);
                fma2(acc2[1][8], hb1, wt);
            }
        }
        __syncthreads();   // all GEMM reads of dup-H done -> region becomes tri bufs

        // ---- Phase 3: 8 pipelined stages of 8 rows, double-buffered ----
        // Thread rows: rb*16 + rg + 8m. Stage st covers rows [8st, 8st+8):
        // writer warps: rb == st>>1, m = st&1; chunk row = rg.
        // write(st+1) overlaps scatter(st); buffers alternate.
        {
            // write stage 0 into buf 0
            if (rb == 0) {
                float* trow = &sSHR[rg * TPAD + wcol];
#pragma unroll
                for (int q = 0; q < 4; ++q) {
                    *reinterpret_cast<u64*>(trow + 16 * q + 4 * cg)     = acc2[0][2 * q];
                    *reinterpret_cast<u64*>(trow + 16 * q + 4 * cg + 2) = acc2[0][2 * q + 1];
                }
                *reinterpret_cast<u64*>(trow + 64 + 2 * cg) = acc2[0][8];
            }
            __syncthreads();

#pragma unroll
            for (int st = 0; st < 8; ++st) {
                // write next stage into the other buffer (overlaps scatter below)
                if (st < 7 && rb == ((st + 1) >> 1)) {
                    const int m = (st + 1) & 1;
                    float* trow = &sSHR[((st + 1) & 1) * TRIBUF + rg * TPAD + wcol];
#pragma unroll
                    for (int q = 0; q < 4; ++q) {
                        *reinterpret_cast<u64*>(trow + 16 * q + 4 * cg)     = acc2[m][2 * q];
                        *reinterpret_cast<u64*>(trow + 16 * q + 4 * cg + 2) = acc2[m][2 * q + 1];
                    }
                    *reinterpret_cast<u64*>(trow + 64 + 2 * cg) = acc2[m][8];
                }
                // prefetch X of next tile (once, early in epilogue)
                if (st == 0 && tile + GRID < NTILES) {
                    int nrow0 = (tile + GRID) * ROWS;
                    if (tid < 512) {
                        int r = tid >> 3, c4 = tid & 7;
                        cp16(sXaddr + (r * XPAD + c4 * 4) * 4,
                             &s[(size_t)(nrow0 + r) * SDIM + c4 * 4]);
                    } else if (tid < 640) {
                        int t2 = tid - 512, r2 = t2 >> 1, d4 = t2 & 1;
                        cp16(sXaddr + (r2 * XPAD + SDIM + d4 * 4) * 4,
                             &a[(size_t)(nrow0 + r2) * ADIM + d4 * 4]);
                    }
                    cp_commit();
                }

                // coalesced scatter of 8 rows (2 quads per thread)
                const float* tb = &sSHR[(st & 1) * TRIBUF];
                float4* out4 = reinterpret_cast<float4*>(out + (size_t)(row0 + st * 8) * 1024);
#pragma unroll
                for (int it = 0; it < 2; ++it) {
                    const int idx = tid + it * NT;
                    const int r  = idx >> 8;
                    const int o4 = idx & 255;
                    const int4 tt = tbl4[o4];
                    const float* tr = &tb[r * TPAD];
                    float v0 = tr[tt.x & 0xffff];
                    float v1 = tr[tt.y & 0xffff];
                    float v2 = tr[tt.z & 0xffff];
                    float v3 = tr[tt.w & 0xffff];
                    if (tt.x >> 16) v0 = __expf(v0);
                    if (tt.y >> 16) v1 = __expf(v1);
                    if (tt.z >> 16) v2 = __expf(v2);
                    if (tt.w >> 16) v3 = __expf(v3);
                    out4[idx] = make_float4(v0, v1, v2, v3);
                }
                if (st == 7) cp_wait0();   // X(t+1) landed before the final barrier
                __syncthreads();
            }
        }
    }
}

extern "C" void kernel_launch(void* const* d_in, const int* in_sizes, int n_in,
                              void* d_out, int out_size) {
    (void)in_sizes; (void)n_in; (void)out_size;
    const float* s  = (const float*)d_in[0];
    const float* a  = (const float*)d_in[1];
    const float* W1 = (const float*)d_in[2];
    const float* b1 = (const float*)d_in[3];
    const float* W2 = (const float*)d_in[4];
    const float* b2 = (const float*)d_in[5];
    float* out = (float*)d_out;

    const size_t smem_bytes = SM_FLOATS * sizeof(float);  // 212608
    cudaFuncSetAttribute(sigma_persist_kernel,
                         cudaFuncAttributeMaxDynamicSharedMemorySize,
                         (int)smem_bytes);
    sigma_persist_kernel<<<GRID, NT, smem_bytes>>>(s, a, W1, b1, W2, b2, out);
}

// round 11
// speedup vs baseline: 1.1804x; 1.1804x over previous
#include <cuda_runtime.h>
#include <cstdint>

// SigmaModel, persistent-CTA, two warp-groups pipelined over alternate tiles.
// h = relu([s,a] @ W1^T + b1); tri = h @ W2^T + b2;
// out[b,i,j] = tri[t(min(i,j),max(i,j))], diag -> exp.
// Group g (16 warps) processes 32-row tiles; group A's epilogue/P1 overlaps
// group B's GEMM via named barriers. W2 staged once, shared read-only.

#define BATCH    131072
#define SDIM     32
#define ADIM     8
#define INDIM    40
#define HID      64
#define TRI      528
#define GROWS    32               // rows per group-tile
#define NT       1024
#define NTG      512              // threads per group
#define GRID     152              // GB300 SM count
#define NTILES   (BATCH / GROWS)  // 4096
#define NPAD     580              // W2 k-major stride (mult of 4)
#define TPAD     578              // tri chunk stride
#define HPAD     66               // H stride (66 mod 32 = 2 -> banked rows)
#define XPAD     40               // X stride (16B-aligned cp.async rows)

// shared memory layout (float offsets)
#define SM_W2    0                // [64][NPAD] = 37120, persists
#define SM_W1    37120            // [40][64] transposed = 2560
#define SM_B1    39680            // [64]
#define SM_B2    39744            // [576]
#define SM_TBL   40320            // int[1024]
#define SM_GRP   41344            // 2 x group region
#define GRP_SZ   8016             // per-group floats: X 1280 + H 2112 + TRI 4624
#define GOFF_X   0
#define GOFF_H   1280
#define GOFF_TRI 3392
#define SM_FLOATS (SM_GRP + 2 * GRP_SZ)   // 57376 floats = 229504 B

typedef unsigned long long u64;

__device__ __forceinline__ u64 pack2(float lo, float hi) {
    u64 r; asm("mov.b64 %0, {%1, %2};" : "=l"(r) : "f"(lo), "f"(hi)); return r;
}
__device__ __forceinline__ void unpack2(u64 v, float& lo, float& hi) {
    asm("mov.b64 {%0, %1}, %2;" : "=f"(lo), "=f"(hi) : "l"(v));
}
__device__ __forceinline__ void fma2(u64& d, u64 a, u64 b) {
    asm("fma.rn.f32x2 %0, %1, %2, %0;" : "+l"(d) : "l"(a), "l"(b));
}
__device__ __forceinline__ uint32_t smem_u32(const void* p) {
    uint32_t r;
    asm("{ .reg .u64 t; cvta.to.shared.u64 t, %1; cvt.u32.u64 %0, t; }" : "=r"(r) : "l"(p));
    return r;
}
__device__ __forceinline__ void cp16(uint32_t dst, const void* src) {
    asm volatile("cp.async.ca.shared.global [%0], [%1], 16;" :: "r"(dst), "l"(src));
}
__device__ __forceinline__ void cp_commit() {
    asm volatile("cp.async.commit_group;" ::: "memory");
}
__device__ __forceinline__ void cp_wait0() {
    asm volatile("cp.async.wait_group 0;" ::: "memory");
}
__device__ __forceinline__ void gbar(int id) {
    asm volatile("bar.sync %0, %1;" :: "r"(id), "r"(NTG) : "memory");
}

__global__ void __launch_bounds__(NT, 1)
sigma_pipe_kernel(const float* __restrict__ s,
                  const float* __restrict__ a,
                  const float* __restrict__ W1,
                  const float* __restrict__ b1,
                  const float* __restrict__ W2,
                  const float* __restrict__ b2,
                  float* __restrict__ out) {
    extern __shared__ float smem[];
    float* sW2  = smem + SM_W2;
    float* sW1  = smem + SM_W1;
    float* sB1  = smem + SM_B1;
    float* sB2  = smem + SM_B2;
    int*   sTbl = (int*)(smem + SM_TBL);

    const int tid = threadIdx.x;

    // ================= one-time staging (whole CTA) =================
    for (int idx = tid; idx < TRI * (HID / 4); idx += NT) {
        int t = idx >> 4, k4 = idx & 15;
        float4 w = *reinterpret_cast<const float4*>(&W2[t * HID + k4 * 4]);
        sW2[(4 * k4 + 0) * NPAD + t] = w.x;
        sW2[(4 * k4 + 1) * NPAD + t] = w.y;
        sW2[(4 * k4 + 2) * NPAD + t] = w.z;
        sW2[(4 * k4 + 3) * NPAD + t] = w.w;
    }
    for (int idx = tid; idx < HID * (NPAD - TRI); idx += NT) {
        int k = idx / (NPAD - TRI), t = TRI + (idx - k * (NPAD - TRI));
        sW2[k * NPAD + t] = 0.0f;
    }
    for (int idx = tid; idx < HID * INDIM; idx += NT) {
        int hh = idx / INDIM, k = idx - hh * INDIM;
        sW1[k * HID + hh] = W1[idx];
    }
    if (tid < HID) sB1[tid] = b1[tid];
    for (int idx = tid; idx < 576; idx += NT)
        sB2[idx] = (idx < TRI) ? b2[idx] : 0.0f;
    for (int o = tid; o < 1024; o += NT) {
        int i = o >> 5, j = o & 31;
        int ii = (i < j) ? i : j;
        int jj = (i < j) ? j : i;
        int t = ii * 32 - ((ii * (ii + 1)) >> 1) + jj;
        sTbl[o] = t | ((i == j) ? (1 << 16) : 0);
    }

    // group setup
    const int g    = tid >> 9;          // 0 or 1
    const int gtid = tid & (NTG - 1);
    float* sX   = smem + SM_GRP + g * GRP_SZ + GOFF_X;
    float* sH   = smem + SM_GRP + g * GRP_SZ + GOFF_H;
    float* sTri = smem + SM_GRP + g * GRP_SZ + GOFF_TRI;
    const uint32_t sXaddr = smem_u32(sX);
    const int barid = 1 + g;

    // prefetch X for this group's first tile
    const int tileStart = blockIdx.x * 2 + g;
    {
        int row0 = tileStart * GROWS;
        if (gtid < 256) {
            int r = gtid >> 3, c4 = gtid & 7;
            cp16(sXaddr + (r * XPAD + c4 * 4) * 4, &s[(size_t)(row0 + r) * SDIM + c4 * 4]);
        } else if (gtid < 320) {
            int t2 = gtid - 256, r2 = t2 >> 1, d4 = t2 & 1;
            cp16(sXaddr + (r2 * XPAD + SDIM + d4 * 4) * 4,
                 &a[(size_t)(row0 + r2) * ADIM + d4 * 4]);
        }
        cp_commit();
    }
    __syncthreads();   // staging + all first prefetches issued; groups now diverge

    // GEMM mapping within group: 16 warps = 2 row-blocks(16r) x 8 col-blocks(72c)
    const int wig  = gtid >> 5, lane = gtid & 31;
    const int rb   = wig >> 3, cb   = wig & 7;
    const int rg   = lane & 7, cg   = lane >> 3;
    const int wcol = cb * 72;
    const int4* tbl4 = reinterpret_cast<const int4*>(sTbl);

    // ================= per-group persistent tile loop =================
    for (int tile = tileStart; tile < NTILES; tile += 2 * GRID) {
        const int row0 = tile * GROWS;

        cp_wait0();
        gbar(barid);   // X(tile) visible to the whole group

        // ---- Phase 1: H = relu(X @ W1^T + b1) ----
        {
            const int r  = gtid >> 4;          // 0..31
            const int hg = (gtid & 15) * 4;    // 4 hidden cols = 2 pairs
            u64 acc[2];
            acc[0] = *reinterpret_cast<const u64*>(&sB1[hg]);
            acc[1] = *reinterpret_cast<const u64*>(&sB1[hg + 2]);
            const float* xrow = &sX[r * XPAD];
#pragma unroll 5
            for (int k = 0; k < INDIM; ++k) {
                u64 xb = pack2(xrow[k], xrow[k]);
                const ulonglong2 w = *reinterpret_cast<const ulonglong2*>(&sW1[k * HID + hg]);
                fma2(acc[0], xb, w.x);
                fma2(acc[1], xb, w.y);
            }
            float* hrow = &sH[r * HPAD + hg];
            float l0, h0, l1, h1;
            unpack2(acc[0], l0, h0);
            unpack2(acc[1], l1, h1);
            hrow[0] = fmaxf(l0, 0.f);
            hrow[1] = fmaxf(h0, 0.f);
            hrow[2] = fmaxf(l1, 0.f);
            hrow[3] = fmaxf(h1, 0.f);
        }
        gbar(barid);   // H visible; sX free

        // ---- prefetch X of next tile (consumed next iteration) ----
        if (tile + 2 * GRID < NTILES) {
            int nrow0 = (tile + 2 * GRID) * GROWS;
            if (gtid < 256) {
                int r = gtid >> 3, c4 = gtid & 7;
                cp16(sXaddr + (r * XPAD + c4 * 4) * 4,
                     &s[(size_t)(nrow0 + r) * SDIM + c4 * 4]);
            } else if (gtid < 320) {
                int t2 = gtid - 256, r2 = t2 >> 1, d4 = t2 & 1;
                cp16(sXaddr + (r2 * XPAD + SDIM + d4 * 4) * 4,
                     &a[(size_t)(nrow0 + r2) * ADIM + d4 * 4]);
            }
            cp_commit();
        }

        // ---- Phase 2: tri = H @ W2^T + b2 (thread tile 2r x 18c) ----
        u64 acc2[2][9];
#pragma unroll
        for (int q = 0; q < 4; ++q) {
            u64 blo = *reinterpret_cast<const u64*>(&sB2[wcol + 16 * q + 4 * cg]);
            u64 bhi = *reinterpret_cast<const u64*>(&sB2[wcol + 16 * q + 4 * cg + 2]);
            acc2[0][2 * q] = blo; acc2[0][2 * q + 1] = bhi;
            acc2[1][2 * q] = blo; acc2[1][2 * q + 1] = bhi;
        }
        {
            u64 bt = *reinterpret_cast<const u64*>(&sB2[wcol + 64 + 2 * cg]);
            acc2[0][8] = bt; acc2[1][8] = bt;
        }

        const float* hbase = &sH[(rb * 16 + rg) * HPAD];
#pragma unroll 4
        for (int k = 0; k < HID; ++k) {
            u64 hb0, hb1;
            {
                float h0 = hbase[k];
                float h1 = hbase[8 * HPAD + k];
                hb0 = pack2(h0, h0);
                hb1 = pack2(h1, h1);
            }
            const float* wr = &sW2[k * NPAD + wcol];
#pragma unroll
            for (int q = 0; q < 4; ++q) {
                const ulonglong2 w = *reinterpret_cast<const ulonglong2*>(wr + 16 * q + 4 * cg);
                fma2(acc2[0][2 * q],     hb0, w.x);
                fma2(acc2[0][2 * q + 1], hb0, w.y);
                fma2(acc2[1][2 * q],     hb1, w.x);
                fma2(acc2[1][2 * q + 1], hb1, w.y);
            }
            {
                const u64 wt = *reinterpret_cast<const u64*>(wr + 64 + 2 * cg);
                fma2(acc2[0][8], hb0, wt);
                fma2(acc2[1][8], hb1, wt);
            }
        }

        // ---- Phase 3: 4 stages of 8 rows via single 8-row chunk ----
        // Thread rows: rb*16 + rg + 8m (m=0,1). Stage st covers [8st, 8st+8):
        // writers: rb == st>>1, m = st&1; chunk row = rg.
#pragma unroll
        for (int st = 0; st < 4; ++st) {
            if (rb == (st >> 1)) {
                const int m = st & 1;
                float* trow = &sTri[rg * TPAD + wcol];
#pragma unroll
                for (int q = 0; q < 4; ++q) {
                    *reinterpret_cast<u64*>(trow + 16 * q + 4 * cg)     = acc2[m][2 * q];
                    *reinterpret_cast<u64*>(trow + 16 * q + 4 * cg + 2) = acc2[m][2 * q + 1];
                }
                *reinterpret_cast<u64*>(trow + 64 + 2 * cg) = acc2[m][8];
            }
            gbar(barid);

            // coalesced scatter of 8 rows (4 quads per thread)
            float4* out4 = reinterpret_cast<float4*>(out + (size_t)(row0 + st * 8) * 1024);
#pragma unroll
            for (int it = 0; it < 4; ++it) {
                const int idx = gtid + it * NTG;
                const int r  = idx >> 8;
                const int o4 = idx & 255;
                const int4 tt = tbl4[o4];
                const float* tr = &sTri[r * TPAD];
                float v0 = tr[tt.x & 0xffff];
                float v1 = tr[tt.y & 0xffff];
                float v2 = tr[tt.z & 0xffff];
                float v3 = tr[tt.w & 0xffff];
                if (tt.x >> 16) v0 = __expf(v0);
                if (tt.y >> 16) v1 = __expf(v1);
                if (tt.z >> 16) v2 = __expf(v2);
                if (tt.w >> 16) v3 = __expf(v3);
                out4[idx] = make_float4(v0, v1, v2, v3);
            }
            gbar(barid);   // WAR: scatter done before next stage overwrites chunk
        }
    }
}

extern "C" void kernel_launch(void* const* d_in, const int* in_sizes, int n_in,
                              void* d_out, int out_size) {
    (void)in_sizes; (void)n_in; (void)out_size;
    const float* s  = (const float*)d_in[0];
    const float* a  = (const float*)d_in[1];
    const float* W1 = (const float*)d_in[2];
    const float* b1 = (const float*)d_in[3];
    const float* W2 = (const float*)d_in[4];
    const float* b2 = (const float*)d_in[5];
    float* out = (float*)d_out;

    const size_t smem_bytes = SM_FLOATS * sizeof(float);  // 229504
    cudaFuncSetAttribute(sigma_pipe_kernel,
                         cudaFuncAttributeMaxDynamicSharedMemorySize,
                         (int)smem_bytes);
    sigma_pipe_kernel<<<GRID, NT, smem_bytes>>>(s, a, W1, b1, W2, b2, out);
}

// round 12
// speedup vs baseline: 1.9730x; 1.6715x over previous
#include <cuda_runtime.h>
#include <cuda_bf16.h>
#include <cstdint>

// SigmaModel via legacy tensor-core path: mma.sync.m16n8k16 bf16, bf16x3 split.
// h = relu([s,a] @ W1^T + b1)   (scalar fp32, tiny)
// tri = h @ W2^T + b2           (HMMA: AhBh + AlBh + AhBl, fp32 accum)
// out[b,i,j] = tri[t(min,max)], diag -> exp.
// 152 persistent CTAs, 1024 threads; W2 staged once as bf16 hi/lo.

#define BATCH   131072
#define SDIM    32
#define ADIM    8
#define INDIM   40
#define HID     64
#define TRI     528
#define ROWS    64                // rows per tile
#define NT      1024
#define GRID    152
#define NTILES  (BATCH / ROWS)    // 2048
#define NCOLS   576               // padded tri cols (8 warps x 72)
#define WS      72                // bf16 row stride for W2/H (rows +4 banks)
#define WS32    36                // same, in u32 words
#define TPAD    584               // tri chunk stride (rows +8 banks)
#define XPAD    40

// ---- smem byte offsets ----
#define OFF_W2H  0                // bf16 [576][WS] = 82944
#define OFF_W2L  82944            // 82944
#define OFF_HH   165888           // bf16 [64][WS] = 9216
#define OFF_HL   175104           // 9216
#define OFF_TRI  184320           // f32 [8][TPAD] = 18688
#define OFF_X    203008           // f32 [64][XPAD] = 10240
#define OFF_W1   213248           // f32 [40][64] = 10240
#define OFF_B1   223488           // f32 [64]
#define OFF_B2   223744           // f32 [576] = 2304
#define OFF_TBL  226048           // int [1024] = 4096
#define SMEM_BYTES 230144

typedef unsigned long long u64;

__device__ __forceinline__ u64 pack2(float lo, float hi) {
    u64 r; asm("mov.b64 %0, {%1, %2};" : "=l"(r) : "f"(lo), "f"(hi)); return r;
}
__device__ __forceinline__ void unpack2(u64 v, float& lo, float& hi) {
    asm("mov.b64 {%0, %1}, %2;" : "=f"(lo), "=f"(hi) : "l"(v));
}
__device__ __forceinline__ void fma2(u64& d, u64 a, u64 b) {
    asm("fma.rn.f32x2 %0, %1, %2, %0;" : "+l"(d) : "l"(a), "l"(b));
}
__device__ __forceinline__ uint32_t smem_u32p(const void* p) {
    uint32_t r;
    asm("{ .reg .u64 t; cvta.to.shared.u64 t, %1; cvt.u32.u64 %0, t; }" : "=r"(r) : "l"(p));
    return r;
}
__device__ __forceinline__ void cp16(uint32_t dst, const void* src) {
    asm volatile("cp.async.ca.shared.global [%0], [%1], 16;" :: "r"(dst), "l"(src));
}
__device__ __forceinline__ void cp_commit() {
    asm volatile("cp.async.commit_group;" ::: "memory");
}
__device__ __forceinline__ void cp_wait0() {
    asm volatile("cp.async.wait_group 0;" ::: "memory");
}
__device__ __forceinline__ void mma_bf16(float* c, uint32_t a0, uint32_t a1,
                                         uint32_t a2, uint32_t a3,
                                         uint32_t b0, uint32_t b1) {
    asm("mma.sync.aligned.m16n8k16.row.col.f32.bf16.bf16.f32 "
        "{%0,%1,%2,%3},{%4,%5,%6,%7},{%8,%9},{%0,%1,%2,%3};"
        : "+f"(c[0]), "+f"(c[1]), "+f"(c[2]), "+f"(c[3])
        : "r"(a0), "r"(a1), "r"(a2), "r"(a3), "r"(b0), "r"(b1));
}
__device__ __forceinline__ uint32_t bfpack(float x, float y) {
    return (uint32_t)__bfloat16_as_ushort(__float2bfloat16_rn(x)) |
           ((uint32_t)__bfloat16_as_ushort(__float2bfloat16_rn(y)) << 16);
}

__global__ void __launch_bounds__(NT, 1)
sigma_mma_kernel(const float* __restrict__ s,
                 const float* __restrict__ a,
                 const float* __restrict__ W1,
                 const float* __restrict__ b1,
                 const float* __restrict__ W2,
                 const float* __restrict__ b2,
                 float* __restrict__ out) {
    extern __shared__ char smem[];
    uint32_t* W2H32 = (uint32_t*)(smem + OFF_W2H);
    uint32_t* W2L32 = (uint32_t*)(smem + OFF_W2L);
    uint32_t* HH32  = (uint32_t*)(smem + OFF_HH);
    uint32_t* HL32  = (uint32_t*)(smem + OFF_HL);
    float*    sTri  = (float*)(smem + OFF_TRI);
    float*    sX    = (float*)(smem + OFF_X);
    float*    sW1   = (float*)(smem + OFF_W1);
    float*    sB1   = (float*)(smem + OFF_B1);
    float*    sB2   = (float*)(smem + OFF_B2);
    int*      sTbl  = (int*)(smem + OFF_TBL);

    const int tid = threadIdx.x;
    const uint32_t sXaddr = smem_u32p(sX);

    // ================= one-time staging =================
    // W2 [528][64] fp32 -> bf16 hi/lo at stride WS
    for (int idx = tid; idx < TRI * 32; idx += NT) {        // 32 u32 words per row
        int t = idx >> 5, kw = idx & 31;
        float2 w = *reinterpret_cast<const float2*>(&W2[t * HID + kw * 2]);
        float h0f = __bfloat162float(__float2bfloat16_rn(w.x));
        float h1f = __bfloat162float(__float2bfloat16_rn(w.y));
        W2H32[t * WS32 + kw] = bfpack(w.x, w.y);
        W2L32[t * WS32 + kw] = bfpack(w.x - h0f, w.y - h1f);
    }
    // zero rows [TRI, NCOLS)
    for (int idx = tid; idx < (NCOLS - TRI) * WS32; idx += NT) {
        int t = TRI + idx / WS32, kw = idx % WS32;
        W2H32[t * WS32 + kw] = 0u;
        W2L32[t * WS32 + kw] = 0u;
    }
    // W1[hh][k] -> sW1[k][hh]
    for (int idx = tid; idx < HID * INDIM; idx += NT) {
        int hh = idx / INDIM, k = idx - hh * INDIM;
        sW1[k * HID + hh] = W1[idx];
    }
    if (tid < HID) sB1[tid] = b1[tid];
    for (int idx = tid; idx < NCOLS; idx += NT)
        sB2[idx] = (idx < TRI) ? b2[idx] : 0.0f;
    for (int o = tid; o < 1024; o += NT) {
        int i = o >> 5, j = o & 31;
        int ii = (i < j) ? i : j;
        int jj = (i < j) ? j : i;
        int t = ii * 32 - ((ii * (ii + 1)) >> 1) + jj;
        sTbl[o] = t | ((i == j) ? (1 << 16) : 0);
    }

    // prefetch X for first tile
    const int tile0 = blockIdx.x;
    {
        int row0 = tile0 * ROWS;
        if (tid < 512) {
            int r = tid >> 3, c4 = tid & 7;
            cp16(sXaddr + (r * XPAD + c4 * 4) * 4, &s[(size_t)(row0 + r) * SDIM + c4 * 4]);
        } else if (tid < 640) {
            int t2 = tid - 512, r2 = t2 >> 1, d4 = t2 & 1;
            cp16(sXaddr + (r2 * XPAD + SDIM + d4 * 4) * 4,
                 &a[(size_t)(row0 + r2) * ADIM + d4 * 4]);
        }
        cp_commit();
    }
    cp_wait0();
    __syncthreads();

    // MMA mapping: 32 warps = 4 M-blocks(16r) x 8 N-blocks(72c = 9 tiles of n8).
    const int wi   = tid >> 5, lane = tid & 31;
    const int rb   = wi >> 3,  cb   = wi & 7;
    const int l4   = lane >> 2, lm  = lane & 3;
    const int wcol = cb * 72;
    const int aBase = (rb * 16 + l4) * WS32 + lm;      // a0 word; a1 +8*WS32; a2 +4
    const int bBase = (wcol + l4) * WS32 + lm;         // ntile j: +j*8*WS32
    const int4* tbl4 = reinterpret_cast<const int4*>(sTbl);

    // ================= persistent tile loop =================
    for (int tile = tile0; tile < NTILES; tile += GRID) {
        const int row0 = tile * ROWS;

        // ---- Phase 1: H = relu(X @ W1^T + b1) -> bf16 hi/lo ----
        {
            const int r  = tid >> 4;           // 0..63
            const int hg = (tid & 15) * 4;     // 4 hidden cols
            u64 acc[2];
            acc[0] = *reinterpret_cast<const u64*>(&sB1[hg]);
            acc[1] = *reinterpret_cast<const u64*>(&sB1[hg + 2]);
            const float* xrow = &sX[r * XPAD];
#pragma unroll 5
            for (int k = 0; k < INDIM; ++k) {
                u64 xb = pack2(xrow[k], xrow[k]);
                const ulonglong2 w = *reinterpret_cast<const ulonglong2*>(&sW1[k * HID + hg]);
                fma2(acc[0], xb, w.x);
                fma2(acc[1], xb, w.y);
            }
            float h0, h1, h2, h3;
            unpack2(acc[0], h0, h1);
            unpack2(acc[1], h2, h3);
            h0 = fmaxf(h0, 0.f); h1 = fmaxf(h1, 0.f);
            h2 = fmaxf(h2, 0.f); h3 = fmaxf(h3, 0.f);
            const int wbase = r * WS32 + (tid & 15) * 2;
            float t0 = __bfloat162float(__float2bfloat16_rn(h0));
            float t1 = __bfloat162float(__float2bfloat16_rn(h1));
            float t2 = __bfloat162float(__float2bfloat16_rn(h2));
            float t3 = __bfloat162float(__float2bfloat16_rn(h3));
            HH32[wbase]     = bfpack(h0, h1);
            HH32[wbase + 1] = bfpack(h2, h3);
            HL32[wbase]     = bfpack(h0 - t0, h1 - t1);
            HL32[wbase + 1] = bfpack(h2 - t2, h3 - t3);
        }
        __syncthreads();   // H visible; sX free for prefetch

        // ---- prefetch X of next tile ----
        if (tile + GRID < NTILES) {
            int nrow0 = (tile + GRID) * ROWS;
            if (tid < 512) {
                int r = tid >> 3, c4 = tid & 7;
                cp16(sXaddr + (r * XPAD + c4 * 4) * 4,
                     &s[(size_t)(nrow0 + r) * SDIM + c4 * 4]);
            } else if (tid < 640) {
                int t2 = tid - 512, r2 = t2 >> 1, d4 = t2 & 1;
                cp16(sXaddr + (r2 * XPAD + SDIM + d4 * 4) * 4,
                     &a[(size_t)(nrow0 + r2) * ADIM + d4 * 4]);
            }
            cp_commit();
        }

        // ---- Phase 2: tri = H @ W2^T + b2 (HMMA, bf16x3) ----
        float c[9][4];
#pragma unroll
        for (int j = 0; j < 9; ++j) {
            float2 bb = *reinterpret_cast<const float2*>(&sB2[wcol + j * 8 + 2 * lm]);
            c[j][0] = bb.x; c[j][1] = bb.y;
            c[j][2] = bb.x; c[j][3] = bb.y;
        }
#pragma unroll
        for (int kk = 0; kk < 4; ++kk) {
            const int ko = kk * 8;
            const uint32_t ah0 = HH32[aBase + ko];
            const uint32_t ah1 = HH32[aBase + 8 * WS32 + ko];
            const uint32_t ah2 = HH32[aBase + ko + 4];
            const uint32_t ah3 = HH32[aBase + 8 * WS32 + ko + 4];
            const uint32_t al0 = HL32[aBase + ko];
            const uint32_t al1 = HL32[aBase + 8 * WS32 + ko];
            const uint32_t al2 = HL32[aBase + ko + 4];
            const uint32_t al3 = HL32[aBase + 8 * WS32 + ko + 4];
#pragma unroll
            for (int j = 0; j < 9; ++j) {
                const int bo = bBase + j * 8 * WS32 + ko;
                const uint32_t bh0 = W2H32[bo];
                const uint32_t bh1 = W2H32[bo + 4];
                const uint32_t bl0 = W2L32[bo];
                const uint32_t bl1 = W2L32[bo + 4];
                mma_bf16(c[j], ah0, ah1, ah2, ah3, bh0, bh1);
                mma_bf16(c[j], al0, al1, al2, al3, bh0, bh1);
                mma_bf16(c[j], ah0, ah1, ah2, ah3, bl0, bl1);
            }
        }

        // ---- Phase 3: 8 stages of 8 rows via smem chunk + table scatter ----
        // C rows: rb*16 + l4 (c0,c1) and rb*16 + 8 + l4 (c2,c3).
        // Stage st covers rows [8st, 8st+8): writers rb == st>>1;
        // even st -> (c0,c1), odd st -> (c2,c3); chunk row = l4.
#pragma unroll
        for (int st = 0; st < 8; ++st) {
            if (rb == (st >> 1)) {
                float* trow = &sTri[l4 * TPAD + wcol + 2 * lm];
                if ((st & 1) == 0) {
#pragma unroll
                    for (int j = 0; j < 9; ++j)
                        *reinterpret_cast<float2*>(trow + j * 8) = make_float2(c[j][0], c[j][1]);
                } else {
#pragma unroll
                    for (int j = 0; j < 9; ++j)
                        *reinterpret_cast<float2*>(trow + j * 8) = make_float2(c[j][2], c[j][3]);
                }
            }
            __syncthreads();

            // coalesced scatter of 8 rows (2 quads per thread)
            float4* out4 = reinterpret_cast<float4*>(out + (size_t)(row0 + st * 8) * 1024);
#pragma unroll
            for (int it = 0; it < 2; ++it) {
                const int idx = tid + it * NT;
                const int r  = idx >> 8;
                const int o4 = idx & 255;
                const int4 tt = tbl4[o4];
                const float* tr = &sTri[r * TPAD];
                float v0 = tr[tt.x & 0xffff];
                float v1 = tr[tt.y & 0xffff];
                float v2 = tr[tt.z & 0xffff];
                float v3 = tr[tt.w & 0xffff];
                if (tt.x >> 16) v0 = __expf(v0);
                if (tt.y >> 16) v1 = __expf(v1);
                if (tt.z >> 16) v2 = __expf(v2);
                if (tt.w >> 16) v3 = __expf(v3);
                out4[idx] = make_float4(v0, v1, v2, v3);
            }
            if (st == 7) cp_wait0();   // X(t+1) landed before final barrier
            __syncthreads();
        }
    }
}

extern "C" void kernel_launch(void* const* d_in, const int* in_sizes, int n_in,
                              void* d_out, int out_size) {
    (void)in_sizes; (void)n_in; (void)out_size;
    const float* s  = (const float*)d_in[0];
    const float* a  = (const float*)d_in[1];
    const float* W1 = (const float*)d_in[2];
    const float* b1 = (const float*)d_in[3];
    const float* W2 = (const float*)d_in[4];
    const float* b2 = (const float*)d_in[5];
    float* out = (float*)d_out;

    cudaFuncSetAttribute(sigma_mma_kernel,
                         cudaFuncAttributeMaxDynamicSharedMemorySize, SMEM_BYTES);
    sigma_mma_kernel<<<GRID, NT, SMEM_BYTES>>>(s, a, W1, b1, W2, b2, out);
}

// round 13
// speedup vs baseline: 2.1214x; 1.0752x over previous
#include <cuda_runtime.h>
#include <cuda_bf16.h>
#include <cstdint>

// SigmaModel via legacy tensor-core path: mma.sync.m16n8k16 bf16, bf16x3 split.
// R13: ldmatrix fragment loads + hoisted scatter constants.
// h = relu([s,a] @ W1^T + b1)   (scalar fp32, tiny)
// tri = h @ W2^T + b2           (HMMA: AhBh + AlBh + AhBl, fp32 accum)
// out[b,i,j] = tri[t(min,max)], diag -> exp.

#define BATCH   131072
#define SDIM    32
#define ADIM    8
#define INDIM   40
#define HID     64
#define TRI     528
#define ROWS    64                // rows per tile
#define NT      1024
#define GRID    152
#define NTILES  (BATCH / ROWS)    // 2048
#define NCOLS   576               // padded tri cols (8 warps x 72)
#define WS32    36                // u32 words per W2/H row (rows +4 banks)
#define TPAD    584               // tri chunk stride
#define XPAD    40

// ---- smem byte offsets ----
#define OFF_W2H  0                // bf16 [576][72] = 82944
#define OFF_W2L  82944
#define OFF_HH   165888           // bf16 [64][72] = 9216
#define OFF_HL   175104
#define OFF_TRI  184320           // f32 [8][TPAD] = 18688
#define OFF_X    203008           // f32 [64][XPAD] = 10240
#define OFF_W1   213248           // f32 [40][64] = 10240
#define OFF_B1   223488
#define OFF_B2   223744           // f32 [576]
#define OFF_TBL  226048           // int [1024]
#define SMEM_BYTES 230144

#define DHL  (OFF_HL - OFF_HH)    // 9216
#define DWL  (OFF_W2L - OFF_W2H)  // 82944

typedef unsigned long long u64;

__device__ __forceinline__ u64 pack2(float lo, float hi) {
    u64 r; asm("mov.b64 %0, {%1, %2};" : "=l"(r) : "f"(lo), "f"(hi)); return r;
}
__device__ __forceinline__ void unpack2(u64 v, float& lo, float& hi) {
    asm("mov.b64 {%0, %1}, %2;" : "=f"(lo), "=f"(hi) : "l"(v));
}
__device__ __forceinline__ void fma2(u64& d, u64 a, u64 b) {
    asm("fma.rn.f32x2 %0, %1, %2, %0;" : "+l"(d) : "l"(a), "l"(b));
}
__device__ __forceinline__ uint32_t smem_u32p(const void* p) {
    uint32_t r;
    asm("{ .reg .u64 t; cvta.to.shared.u64 t, %1; cvt.u32.u64 %0, t; }" : "=r"(r) : "l"(p));
    return r;
}
__device__ __forceinline__ void cp16(uint32_t dst, const void* src) {
    asm volatile("cp.async.ca.shared.global [%0], [%1], 16;" :: "r"(dst), "l"(src));
}
__device__ __forceinline__ void cp_commit() {
    asm volatile("cp.async.commit_group;" ::: "memory");
}
__device__ __forceinline__ void cp_wait0() {
    asm volatile("cp.async.wait_group 0;" ::: "memory");
}
__device__ __forceinline__ void ldsm4(uint32_t* r, uint32_t a) {
    asm volatile("ldmatrix.sync.aligned.m8n8.x4.shared.b16 {%0,%1,%2,%3}, [%4];"
                 : "=r"(r[0]), "=r"(r[1]), "=r"(r[2]), "=r"(r[3]) : "r"(a));
}
__device__ __forceinline__ void ldsm2(uint32_t* r, uint32_t a) {
    asm volatile("ldmatrix.sync.aligned.m8n8.x2.shared.b16 {%0,%1}, [%2];"
                 : "=r"(r[0]), "=r"(r[1]) : "r"(a));
}
__device__ __forceinline__ void mma_bf16(float* c, const uint32_t* a,
                                         uint32_t b0, uint32_t b1) {
    asm("mma.sync.aligned.m16n8k16.row.col.f32.bf16.bf16.f32 "
        "{%0,%1,%2,%3},{%4,%5,%6,%7},{%8,%9},{%0,%1,%2,%3};"
        : "+f"(c[0]), "+f"(c[1]), "+f"(c[2]), "+f"(c[3])
        : "r"(a[0]), "r"(a[1]), "r"(a[2]), "r"(a[3]), "r"(b0), "r"(b1));
}
__device__ __forceinline__ uint32_t bfpack(float x, float y) {
    return (uint32_t)__bfloat16_as_ushort(__float2bfloat16_rn(x)) |
           ((uint32_t)__bfloat16_as_ushort(__float2bfloat16_rn(y)) << 16);
}

__global__ void __launch_bounds__(NT, 1)
sigma_mma_kernel(const float* __restrict__ s,
                 const float* __restrict__ a,
                 const float* __restrict__ W1,
                 const float* __restrict__ b1,
                 const float* __restrict__ W2,
                 const float* __restrict__ b2,
                 float* __restrict__ out) {
    extern __shared__ char smem[];
    uint32_t* W2H32 = (uint32_t*)(smem + OFF_W2H);
    uint32_t* W2L32 = (uint32_t*)(smem + OFF_W2L);
    uint32_t* HH32  = (uint32_t*)(smem + OFF_HH);
    uint32_t* HL32  = (uint32_t*)(smem + OFF_HL);
    float*    sTri  = (float*)(smem + OFF_TRI);
    float*    sX    = (float*)(smem + OFF_X);
    float*    sW1   = (float*)(smem + OFF_W1);
    float*    sB1   = (float*)(smem + OFF_B1);
    float*    sB2   = (float*)(smem + OFF_B2);
    int*      sTbl  = (int*)(smem + OFF_TBL);

    const int tid = threadIdx.x;
    const uint32_t sXaddr = smem_u32p(sX);

    // ================= one-time staging =================
    for (int idx = tid; idx < TRI * 32; idx += NT) {
        int t = idx >> 5, kw = idx & 31;
        float2 w = *reinterpret_cast<const float2*>(&W2[t * HID + kw * 2]);
        float h0f = __bfloat162float(__float2bfloat16_rn(w.x));
        float h1f = __bfloat162float(__float2bfloat16_rn(w.y));
        W2H32[t * WS32 + kw] = bfpack(w.x, w.y);
        W2L32[t * WS32 + kw] = bfpack(w.x - h0f, w.y - h1f);
    }
    for (int idx = tid; idx < (NCOLS - TRI) * WS32; idx += NT) {
        int t = TRI + idx / WS32, kw = idx % WS32;
        W2H32[t * WS32 + kw] = 0u;
        W2L32[t * WS32 + kw] = 0u;
    }
    for (int idx = tid; idx < HID * INDIM; idx += NT) {
        int hh = idx / INDIM, k = idx - hh * INDIM;
        sW1[k * HID + hh] = W1[idx];
    }
    if (tid < HID) sB1[tid] = b1[tid];
    for (int idx = tid; idx < NCOLS; idx += NT)
        sB2[idx] = (idx < TRI) ? b2[idx] : 0.0f;
    for (int o = tid; o < 1024; o += NT) {
        int i = o >> 5, j = o & 31;
        int ii = (i < j) ? i : j;
        int jj = (i < j) ? j : i;
        int t = ii * 32 - ((ii * (ii + 1)) >> 1) + jj;
        sTbl[o] = t | ((i == j) ? (1 << 16) : 0);
    }

    // prefetch X for first tile
    const int tile0 = blockIdx.x;
    {
        int row0 = tile0 * ROWS;
        if (tid < 512) {
            int r = tid >> 3, c4 = tid & 7;
            cp16(sXaddr + (r * XPAD + c4 * 4) * 4, &s[(size_t)(row0 + r) * SDIM + c4 * 4]);
        } else if (tid < 640) {
            int t2 = tid - 512, r2 = t2 >> 1, d4 = t2 & 1;
            cp16(sXaddr + (r2 * XPAD + SDIM + d4 * 4) * 4,
                 &a[(size_t)(row0 + r2) * ADIM + d4 * 4]);
        }
        cp_commit();
    }
    cp_wait0();
    __syncthreads();

    // MMA mapping: 32 warps = 4 M-blocks(16r) x 8 N-blocks(72c = 9 n8-tiles).
    const int wi   = tid >> 5, lane = tid & 31;
    const int rb   = wi >> 3,  cb   = wi & 7;
    const int l4   = lane >> 2, lm  = lane & 3;
    const int wcol = cb * 72;

    // ldmatrix per-lane base addresses (bytes)
    const uint32_t hhBase = smem_u32p(HH32);
    const uint32_t w2Base = smem_u32p(W2H32);
    // A x4: lanes 0-15 -> rows rb*16+(lane&15), k0-7; lanes 16-31 -> +16B (k8-15)
    const uint32_t aAddr = hhBase +
        (((rb * 16 + (lane & 15)) * WS32 + ((lane >> 4) << 2)) << 2);
    // B x4 (j-pair p): L0-7 row j=(2p), k0-7; L8-15 +16B; L16-23 row j=2p+1; L24-31 +16B
    const uint32_t bAddr = w2Base +
        (((wcol + (lane & 7) + ((lane & 16) >> 1)) * WS32 + (((lane >> 3) & 1) << 2)) << 2);
    // B x2 (j=8): lanes 0-15 used
    const uint32_t b8Addr = w2Base +
        (((wcol + 64 + (lane & 7)) * WS32 + (((lane >> 3) & 1) << 2)) << 2);

    // hoisted scatter constants (tile-invariant)
    const int4 tt = ((const int4*)sTbl)[tid & 255];
    const int to0 = tt.x & 0xffff, to1 = tt.y & 0xffff;
    const int to2 = tt.z & 0xffff, to3 = tt.w & 0xffff;
    const int fl0 = tt.x >> 16, fl1 = tt.y >> 16, fl2 = tt.z >> 16, fl3 = tt.w >> 16;
    const float* trA = &sTri[(tid >> 8) * TPAD];        // chunk rows 0..3
    const float* trB = &sTri[((tid >> 8) + 4) * TPAD];  // chunk rows 4..7
    float* const trW = &sTri[l4 * TPAD + wcol + 2 * lm];  // writer ptr

    // ================= persistent tile loop =================
    for (int tile = tile0; tile < NTILES; tile += GRID) {
        const int row0 = tile * ROWS;

        // ---- Phase 1: H = relu(X @ W1^T + b1) -> bf16 hi/lo ----
        {
            const int r  = tid >> 4;
            const int hg = (tid & 15) * 4;
            u64 acc[2];
            acc[0] = *reinterpret_cast<const u64*>(&sB1[hg]);
            acc[1] = *reinterpret_cast<const u64*>(&sB1[hg + 2]);
            const float* xrow = &sX[r * XPAD];
#pragma unroll 5
            for (int k = 0; k < INDIM; ++k) {
                u64 xb = pack2(xrow[k], xrow[k]);
                const ulonglong2 w = *reinterpret_cast<const ulonglong2*>(&sW1[k * HID + hg]);
                fma2(acc[0], xb, w.x);
                fma2(acc[1], xb, w.y);
            }
            float h0, h1, h2, h3;
            unpack2(acc[0], h0, h1);
            unpack2(acc[1], h2, h3);
            h0 = fmaxf(h0, 0.f); h1 = fmaxf(h1, 0.f);
            h2 = fmaxf(h2, 0.f); h3 = fmaxf(h3, 0.f);
            const int wbase = r * WS32 + (tid & 15) * 2;
            float t0 = __bfloat162float(__float2bfloat16_rn(h0));
            float t1 = __bfloat162float(__float2bfloat16_rn(h1));
            float t2 = __bfloat162float(__float2bfloat16_rn(h2));
            float t3 = __bfloat162float(__float2bfloat16_rn(h3));
            HH32[wbase]     = bfpack(h0, h1);
            HH32[wbase + 1] = bfpack(h2, h3);
            HL32[wbase]     = bfpack(h0 - t0, h1 - t1);
            HL32[wbase + 1] = bfpack(h2 - t2, h3 - t3);
        }
        __syncthreads();   // H visible; sX free for prefetch

        // ---- prefetch X of next tile ----
        if (tile + GRID < NTILES) {
            int nrow0 = (tile + GRID) * ROWS;
            if (tid < 512) {
                int r = tid >> 3, c4 = tid & 7;
                cp16(sXaddr + (r * XPAD + c4 * 4) * 4,
                     &s[(size_t)(nrow0 + r) * SDIM + c4 * 4]);
            } else if (tid < 640) {
                int t2 = tid - 512, r2 = t2 >> 1, d4 = t2 & 1;
                cp16(sXaddr + (r2 * XPAD + SDIM + d4 * 4) * 4,
                     &a[(size_t)(nrow0 + r2) * ADIM + d4 * 4]);
            }
            cp_commit();
        }

        // ---- Phase 2: tri = H @ W2^T + b2 (HMMA via ldmatrix, bf16x3) ----
        float c[9][4];
#pragma unroll
        for (int j = 0; j < 9; ++j) {
            float2 bb = *reinterpret_cast<const float2*>(&sB2[wcol + j * 8 + 2 * lm]);
            c[j][0] = bb.x; c[j][1] = bb.y;
            c[j][2] = bb.x; c[j][3] = bb.y;
        }
#pragma unroll
        for (int kk = 0; kk < 4; ++kk) {
            const uint32_t kb = kk * 32;       // byte advance per k-block
            uint32_t ah[4], al[4];
            ldsm4(ah, aAddr + kb);
            ldsm4(al, aAddr + DHL + kb);
#pragma unroll
            for (int p = 0; p < 4; ++p) {
                uint32_t bh[4], bl[4];
                ldsm4(bh, bAddr + p * 2304 + kb);
                ldsm4(bl, bAddr + DWL + p * 2304 + kb);
                mma_bf16(c[2 * p],     ah, bh[0], bh[1]);
                mma_bf16(c[2 * p],     al, bh[0], bh[1]);
                mma_bf16(c[2 * p],     ah, bl[0], bl[1]);
                mma_bf16(c[2 * p + 1], ah, bh[2], bh[3]);
                mma_bf16(c[2 * p + 1], al, bh[2], bh[3]);
                mma_bf16(c[2 * p + 1], ah, bl[2], bl[3]);
            }
            {
                uint32_t bh[2], bl[2];
                ldsm2(bh, b8Addr + kb);
                ldsm2(bl, b8Addr + DWL + kb);
                mma_bf16(c[8], ah, bh[0], bh[1]);
                mma_bf16(c[8], al, bh[0], bh[1]);
                mma_bf16(c[8], ah, bl[0], bl[1]);
            }
        }

        // ---- Phase 3: 8 stages of 8 rows via smem chunk + table scatter ----
#pragma unroll
        for (int st = 0; st < 8; ++st) {
            if (rb == (st >> 1)) {
                if ((st & 1) == 0) {
#pragma unroll
                    for (int j = 0; j < 9; ++j)
                        *reinterpret_cast<float2*>(trW + j * 8) = make_float2(c[j][0], c[j][1]);
                } else {
#pragma unroll
                    for (int j = 0; j < 9; ++j)
                        *reinterpret_cast<float2*>(trW + j * 8) = make_float2(c[j][2], c[j][3]);
                }
            }
            __syncthreads();

            float4* out4 = reinterpret_cast<float4*>(out + (size_t)(row0 + st * 8) * 1024);
            {
                float v0 = trA[to0], v1 = trA[to1], v2 = trA[to2], v3 = trA[to3];
                if (fl0) v0 = __expf(v0);
                if (fl1) v1 = __expf(v1);
                if (fl2) v2 = __expf(v2);
                if (fl3) v3 = __expf(v3);
                out4[tid] = make_float4(v0, v1, v2, v3);
            }
            {
                float v0 = trB[to0], v1 = trB[to1], v2 = trB[to2], v3 = trB[to3];
                if (fl0) v0 = __expf(v0);
                if (fl1) v1 = __expf(v1);
                if (fl2) v2 = __expf(v2);
                if (fl3) v3 = __expf(v3);
                out4[tid + NT] = make_float4(v0, v1, v2, v3);
            }
            if (st == 7) cp_wait0();
            __syncthreads();
        }
    }
}

extern "C" void kernel_launch(void* const* d_in, const int* in_sizes, int n_in,
                              void* d_out, int out_size) {
    (void)in_sizes; (void)n_in; (void)out_size;
    const float* s  = (const float*)d_in[0];
    const float* a  = (const float*)d_in[1];
    const float* W1 = (const float*)d_in[2];
    const float* b1 = (const float*)d_in[3];
    const float* W2 = (const float*)d_in[4];
    const float* b2 = (const float*)d_in[5];
    float* out = (float*)d_out;

    cudaFuncSetAttribute(sigma_mma_kernel,
                         cudaFuncAttributeMaxDynamicSharedMemorySize, SMEM_BYTES);
    sigma_mma_kernel<<<GRID, NT, SMEM_BYTES>>>(s, a, W1, b1, W2, b2, out);
}

// round 14
// speedup vs baseline: 2.3024x; 1.0854x over previous
#include <cuda_runtime.h>
#include <cuda_fp16.h>
#include <cstdint>

// SigmaModel via tensor cores: mma.sync.m16n8k16 fp16, 2-term split.
// h = relu([s,a] @ W1^T + b1)   (scalar fp32)
// tri = h @ W2^T + b2           (HMMA: Hh*Wh + Hl*Wh, fp32 accum; W2 in fp16)
// out[b,i,j] = tri[t(min,max)], diag -> exp.
// 152 persistent CTAs, 1024 threads; 16-row epilogue chunks (4 stages).

#define BATCH   131072
#define SDIM    32
#define ADIM    8
#define INDIM   40
#define HID     64
#define TRI     528
#define ROWS    64                // rows per tile
#define NT      1024
#define GRID    152
#define NTILES  (BATCH / ROWS)    // 2048
#define NCOLS   576               // padded tri cols (8 warps x 72)
#define WS32    36                // u32 words per W2/H row (rows +4 banks)
#define TPAD    584               // tri chunk stride
#define XPAD    40

// ---- smem byte offsets ----
#define OFF_W2H  0                // fp16 [576][72] = 82944
#define OFF_HH   82944            // fp16 [64][72] = 9216
#define OFF_HL   92160            // 9216
#define OFF_TRI  101376           // f32 [16][TPAD] = 37376
#define OFF_X    138752           // f32 [64][XPAD] = 10240
#define OFF_W1   148992           // f32 [40][64] = 10240
#define OFF_B1   159232           // f32 [64]
#define OFF_B2   159488           // f32 [576] = 2304
#define OFF_TBL  161792           // int [1024] = 4096
#define SMEM_BYTES 165888

#define DHL  (OFF_HL - OFF_HH)    // 9216

typedef unsigned long long u64;

__device__ __forceinline__ u64 pack2(float lo, float hi) {
    u64 r; asm("mov.b64 %0, {%1, %2};" : "=l"(r) : "f"(lo), "f"(hi)); return r;
}
__device__ __forceinline__ void unpack2(u64 v, float& lo, float& hi) {
    asm("mov.b64 {%0, %1}, %2;" : "=f"(lo), "=f"(hi) : "l"(v));
}
__device__ __forceinline__ void fma2(u64& d, u64 a, u64 b) {
    asm("fma.rn.f32x2 %0, %1, %2, %0;" : "+l"(d) : "l"(a), "l"(b));
}
__device__ __forceinline__ uint32_t smem_u32p(const void* p) {
    uint32_t r;
    asm("{ .reg .u64 t; cvta.to.shared.u64 t, %1; cvt.u32.u64 %0, t; }" : "=r"(r) : "l"(p));
    return r;
}
__device__ __forceinline__ void cp16(uint32_t dst, const void* src) {
    asm volatile("cp.async.ca.shared.global [%0], [%1], 16;" :: "r"(dst), "l"(src));
}
__device__ __forceinline__ void cp_commit() {
    asm volatile("cp.async.commit_group;" ::: "memory");
}
__device__ __forceinline__ void cp_wait0() {
    asm volatile("cp.async.wait_group 0;" ::: "memory");
}
__device__ __forceinline__ void ldsm4(uint32_t* r, uint32_t a) {
    asm volatile("ldmatrix.sync.aligned.m8n8.x4.shared.b16 {%0,%1,%2,%3}, [%4];"
                 : "=r"(r[0]), "=r"(r[1]), "=r"(r[2]), "=r"(r[3]) : "r"(a));
}
__device__ __forceinline__ void ldsm2(uint32_t* r, uint32_t a) {
    asm volatile("ldmatrix.sync.aligned.m8n8.x2.shared.b16 {%0,%1}, [%2];"
                 : "=r"(r[0]), "=r"(r[1]) : "r"(a));
}
__device__ __forceinline__ void mma_f16(float* c, const uint32_t* a,
                                        uint32_t b0, uint32_t b1) {
    asm("mma.sync.aligned.m16n8k16.row.col.f32.f16.f16.f32 "
        "{%0,%1,%2,%3},{%4,%5,%6,%7},{%8,%9},{%0,%1,%2,%3};"
        : "+f"(c[0]), "+f"(c[1]), "+f"(c[2]), "+f"(c[3])
        : "r"(a[0]), "r"(a[1]), "r"(a[2]), "r"(a[3]), "r"(b0), "r"(b1));
}
__device__ __forceinline__ uint32_t hfpack(float x, float y) {
    __half2 h = __floats2half2_rn(x, y);
    return *reinterpret_cast<uint32_t*>(&h);
}
__device__ __forceinline__ float hround(float x) {
    return __half2float(__float2half_rn(x));
}

__global__ void __launch_bounds__(NT, 1)
sigma_mma_kernel(const float* __restrict__ s,
                 const float* __restrict__ a,
                 const float* __restrict__ W1,
                 const float* __restrict__ b1,
                 const float* __restrict__ W2,
                 const float* __restrict__ b2,
                 float* __restrict__ out) {
    extern __shared__ char smem[];
    uint32_t* W2H32 = (uint32_t*)(smem + OFF_W2H);
    uint32_t* HH32  = (uint32_t*)(smem + OFF_HH);
    uint32_t* HL32  = (uint32_t*)(smem + OFF_HL);
    float*    sTri  = (float*)(smem + OFF_TRI);
    float*    sX    = (float*)(smem + OFF_X);
    float*    sW1   = (float*)(smem + OFF_W1);
    float*    sB1   = (float*)(smem + OFF_B1);
    float*    sB2   = (float*)(smem + OFF_B2);
    int*      sTbl  = (int*)(smem + OFF_TBL);

    const int tid = threadIdx.x;
    const uint32_t sXaddr = smem_u32p(sX);

    // ================= one-time staging =================
    // W2 [528][64] fp32 -> fp16 at row stride 72 halves (36 u32 words)
    for (int idx = tid; idx < TRI * 32; idx += NT) {
        int t = idx >> 5, kw = idx & 31;
        float2 w = *reinterpret_cast<const float2*>(&W2[t * HID + kw * 2]);
        W2H32[t * WS32 + kw] = hfpack(w.x, w.y);
    }
    for (int idx = tid; idx < (NCOLS - TRI) * WS32; idx += NT) {
        int t = TRI + idx / WS32, kw = idx % WS32;
        W2H32[t * WS32 + kw] = 0u;
    }
    for (int idx = tid; idx < HID * INDIM; idx += NT) {
        int hh = idx / INDIM, k = idx - hh * INDIM;
        sW1[k * HID + hh] = W1[idx];
    }
    if (tid < HID) sB1[tid] = b1[tid];
    for (int idx = tid; idx < NCOLS; idx += NT)
        sB2[idx] = (idx < TRI) ? b2[idx] : 0.0f;
    for (int o = tid; o < 1024; o += NT) {
        int i = o >> 5, j = o & 31;
        int ii = (i < j) ? i : j;
        int jj = (i < j) ? j : i;
        int t = ii * 32 - ((ii * (ii + 1)) >> 1) + jj;
        sTbl[o] = t | ((i == j) ? (1 << 16) : 0);
    }

    // prefetch X for first tile
    const int tile0 = blockIdx.x;
    {
        int row0 = tile0 * ROWS;
        if (tid < 512) {
            int r = tid >> 3, c4 = tid & 7;
            cp16(sXaddr + (r * XPAD + c4 * 4) * 4, &s[(size_t)(row0 + r) * SDIM + c4 * 4]);
        } else if (tid < 640) {
            int t2 = tid - 512, r2 = t2 >> 1, d4 = t2 & 1;
            cp16(sXaddr + (r2 * XPAD + SDIM + d4 * 4) * 4,
                 &a[(size_t)(row0 + r2) * ADIM + d4 * 4]);
        }
        cp_commit();
    }
    cp_wait0();
    __syncthreads();

    // MMA mapping: 32 warps = 4 M-blocks(16r) x 8 N-blocks(72c = 9 n8-tiles).
    const int wi   = tid >> 5, lane = tid & 31;
    const int rb   = wi >> 3,  cb   = wi & 7;
    const int l4   = lane >> 2, lm  = lane & 3;
    const int wcol = cb * 72;

    const uint32_t hhBase = smem_u32p(HH32);
    const uint32_t w2Base = smem_u32p(W2H32);
    const uint32_t aAddr = hhBase +
        (((rb * 16 + (lane & 15)) * WS32 + ((lane >> 4) << 2)) << 2);
    const uint32_t bAddr = w2Base +
        (((wcol + (lane & 7) + ((lane & 16) >> 1)) * WS32 + (((lane >> 3) & 1) << 2)) << 2);
    const uint32_t b8Addr = w2Base +
        (((wcol + 64 + (lane & 7)) * WS32 + (((lane >> 3) & 1) << 2)) << 2);

    // hoisted scatter constants (tile-invariant)
    const int4 tt = ((const int4*)sTbl)[tid & 255];
    const int to0 = tt.x & 0xffff, to1 = tt.y & 0xffff;
    const int to2 = tt.z & 0xffff, to3 = tt.w & 0xffff;
    const int fl0 = tt.x >> 16, fl1 = tt.y >> 16, fl2 = tt.z >> 16, fl3 = tt.w >> 16;
    const float* const trBase = &sTri[(tid >> 8) * TPAD];
    float* const trW0 = &sTri[l4 * TPAD + wcol + 2 * lm];        // rows 0..7 of chunk
    float* const trW1 = trW0 + 8 * TPAD;                          // rows 8..15

    // ================= persistent tile loop =================
    for (int tile = tile0; tile < NTILES; tile += GRID) {
        const int row0 = tile * ROWS;

        // ---- Phase 1: H = relu(X @ W1^T + b1) -> fp16 hi/lo ----
        {
            const int r  = tid >> 4;
            const int hg = (tid & 15) * 4;
            u64 acc[2];
            acc[0] = *reinterpret_cast<const u64*>(&sB1[hg]);
            acc[1] = *reinterpret_cast<const u64*>(&sB1[hg + 2]);
            const float* xrow = &sX[r * XPAD];
#pragma unroll 5
            for (int k = 0; k < INDIM; ++k) {
                u64 xb = pack2(xrow[k], xrow[k]);
                const ulonglong2 w = *reinterpret_cast<const ulonglong2*>(&sW1[k * HID + hg]);
                fma2(acc[0], xb, w.x);
                fma2(acc[1], xb, w.y);
            }
            float h0, h1, h2, h3;
            unpack2(acc[0], h0, h1);
            unpack2(acc[1], h2, h3);
            h0 = fmaxf(h0, 0.f); h1 = fmaxf(h1, 0.f);
            h2 = fmaxf(h2, 0.f); h3 = fmaxf(h3, 0.f);
            const int wbase = (tid >> 4) * WS32 + (tid & 15) * 2;
            HH32[wbase]     = hfpack(h0, h1);
            HH32[wbase + 1] = hfpack(h2, h3);
            HL32[wbase]     = hfpack(h0 - hround(h0), h1 - hround(h1));
            HL32[wbase + 1] = hfpack(h2 - hround(h2), h3 - hround(h3));
        }
        __syncthreads();   // H visible; sX free for prefetch

        // ---- prefetch X of next tile ----
        if (tile + GRID < NTILES) {
            int nrow0 = (tile + GRID) * ROWS;
            if (tid < 512) {
                int r = tid >> 3, c4 = tid & 7;
                cp16(sXaddr + (r * XPAD + c4 * 4) * 4,
                     &s[(size_t)(nrow0 + r) * SDIM + c4 * 4]);
            } else if (tid < 640) {
                int t2 = tid - 512, r2 = t2 >> 1, d4 = t2 & 1;
                cp16(sXaddr + (r2 * XPAD + SDIM + d4 * 4) * 4,
                     &a[(size_t)(nrow0 + r2) * ADIM + d4 * 4]);
            }
            cp_commit();
        }

        // ---- Phase 2: tri = H @ W2^T + b2 (HMMA fp16 2-term) ----
        float c[9][4];
#pragma unroll
        for (int j = 0; j < 9; ++j) {
            float2 bb = *reinterpret_cast<const float2*>(&sB2[wcol + j * 8 + 2 * lm]);
            c[j][0] = bb.x; c[j][1] = bb.y;
            c[j][2] = bb.x; c[j][3] = bb.y;
        }
#pragma unroll
        for (int kk = 0; kk < 4; ++kk) {
            const uint32_t kb = kk * 32;       // byte advance per k-block
            uint32_t ah[4], al[4];
            ldsm4(ah, aAddr + kb);
            ldsm4(al, aAddr + DHL + kb);
#pragma unroll
            for (int p = 0; p < 4; ++p) {
                uint32_t bh[4];
                ldsm4(bh, bAddr + p * 2304 + kb);
                mma_f16(c[2 * p],     ah, bh[0], bh[1]);
                mma_f16(c[2 * p],     al, bh[0], bh[1]);
                mma_f16(c[2 * p + 1], ah, bh[2], bh[3]);
                mma_f16(c[2 * p + 1], al, bh[2], bh[3]);
            }
            {
                uint32_t bh[2];
                ldsm2(bh, b8Addr + kb);
                mma_f16(c[8], ah, bh[0], bh[1]);
                mma_f16(c[8], al, bh[0], bh[1]);
            }
        }

        // ---- Phase 3: 4 stages of 16 rows via smem chunk + table scatter ----
        // Stage st covers rows [16st, 16st+16) = M-block st.
        // Writer warps rb==st dump both C halves (rows l4 and l4+8 of chunk).
#pragma unroll
        for (int st = 0; st < 4; ++st) {
            if (rb == st) {
#pragma unroll
                for (int j = 0; j < 9; ++j) {
                    *reinterpret_cast<float2*>(trW0 + j * 8) = make_float2(c[j][0], c[j][1]);
                    *reinterpret_cast<float2*>(trW1 + j * 8) = make_float2(c[j][2], c[j][3]);
                }
            }
            __syncthreads();

            float4* out4 = reinterpret_cast<float4*>(out + (size_t)(row0 + st * 16) * 1024);
#pragma unroll
            for (int it = 0; it < 4; ++it) {
                const float* tr = trBase + it * 4 * TPAD;
                float v0 = tr[to0], v1 = tr[to1], v2 = tr[to2], v3 = tr[to3];
                if (fl0) v0 = __expf(v0);
                if (fl1) v1 = __expf(v1);
                if (fl2) v2 = __expf(v2);
                if (fl3) v3 = __expf(v3);
                out4[tid + it * NT] = make_float4(v0, v1, v2, v3);
            }
            if (st == 3) cp_wait0();
            __syncthreads();
        }
    }
}

extern "C" void kernel_launch(void* const* d_in, const int* in_sizes, int n_in,
                              void* d_out, int out_size) {
    (void)in_sizes; (void)n_in; (void)out_size;
    const float* s  = (const float*)d_in[0];
    const float* a  = (const float*)d_in[1];
    const float* W1 = (const float*)d_in[2];
    const float* b1 = (const float*)d_in[3];
    const float* W2 = (const float*)d_in[4];
    const float* b2 = (const float*)d_in[5];
    float* out = (float*)d_out;

    cudaFuncSetAttribute(sigma_mma_kernel,
                         cudaFuncAttributeMaxDynamicSharedMemorySize, SMEM_BYTES);
    sigma_mma_kernel<<<GRID, NT, SMEM_BYTES>>>(s, a, W1, b1, W2, b2, out);
}

// round 15
// speedup vs baseline: 2.5428x; 1.1044x over previous
#include <cuda_runtime.h>
#include <cuda_fp16.h>
#include <cstdint>

// SigmaModel via tensor cores: mma.sync.m16n8k16 fp16, single-term H + fp16 W2.
// h = relu([s,a] @ W1^T + b1)   (scalar fp32, broadcast-tiled, -> fp16)
// tri = h @ W2^T + b2           (HMMA fp32 accum)
// out[b,i,j] = tri[t(min,max)], diag -> exp.
// 152 persistent CTAs, 1024 threads; 16-row epilogue chunks.

#define BATCH   131072
#define SDIM    32
#define ADIM    8
#define INDIM   40
#define HID     64
#define TRI     528
#define ROWS    64                // rows per tile
#define NT      1024
#define GRID    152
#define NTILES  (BATCH / ROWS)    // 2048
#define NCOLS   576               // padded tri cols (8 warps x 72)
#define WS32    36                // u32 words per W2/H row (rows +4 banks)
#define TPAD    584               // tri chunk stride
#define XPAD    44                // X/W1 row stride (44 mod 32 = 12 -> banked)

// ---- smem byte offsets ----
#define OFF_W2H  0                // fp16 [576][72] = 82944
#define OFF_HH   82944            // fp16 [64][72] = 9216
#define OFF_TRI  92160            // f32 [16][TPAD] = 37376
#define OFF_X    129536           // f32 [64][44] = 11264
#define OFF_W1   140800           // f32 [64][44] = 11264 (W1 native k-major)
#define OFF_B1   152064           // f32 [64]
#define OFF_B2   152320           // f32 [576] = 2304
#define OFF_TBL  154624           // int [1024] = 4096
#define SMEM_BYTES 158720

typedef unsigned long long u64;

__device__ __forceinline__ void unpack2(u64 v, float& lo, float& hi) {
    asm("mov.b64 {%0, %1}, %2;" : "=f"(lo), "=f"(hi) : "l"(v));
}
__device__ __forceinline__ u64 pack2(float lo, float hi) {
    u64 r; asm("mov.b64 %0, {%1, %2};" : "=l"(r) : "f"(lo), "f"(hi)); return r;
}
__device__ __forceinline__ void fma2(u64& d, u64 a, u64 b) {
    asm("fma.rn.f32x2 %0, %1, %2, %0;" : "+l"(d) : "l"(a), "l"(b));
}
__device__ __forceinline__ uint32_t smem_u32p(const void* p) {
    uint32_t r;
    asm("{ .reg .u64 t; cvta.to.shared.u64 t, %1; cvt.u32.u64 %0, t; }" : "=r"(r) : "l"(p));
    return r;
}
__device__ __forceinline__ void cp16(uint32_t dst, const void* src) {
    asm volatile("cp.async.ca.shared.global [%0], [%1], 16;" :: "r"(dst), "l"(src));
}
__device__ __forceinline__ void cp_commit() {
    asm volatile("cp.async.commit_group;" ::: "memory");
}
__device__ __forceinline__ void cp_wait0() {
    asm volatile("cp.async.wait_group 0;" ::: "memory");
}
__device__ __forceinline__ void ldsm4(uint32_t* r, uint32_t a) {
    asm volatile("ldmatrix.sync.aligned.m8n8.x4.shared.b16 {%0,%1,%2,%3}, [%4];"
                 : "=r"(r[0]), "=r"(r[1]), "=r"(r[2]), "=r"(r[3]) : "r"(a));
}
__device__ __forceinline__ void ldsm2(uint32_t* r, uint32_t a) {
    asm volatile("ldmatrix.sync.aligned.m8n8.x2.shared.b16 {%0,%1}, [%2];"
                 : "=r"(r[0]), "=r"(r[1]) : "r"(a));
}
__device__ __forceinline__ void mma_f16(float* c, const uint32_t* a,
                                        uint32_t b0, uint32_t b1) {
    asm("mma.sync.aligned.m16n8k16.row.col.f32.f16.f16.f32 "
        "{%0,%1,%2,%3},{%4,%5,%6,%7},{%8,%9},{%0,%1,%2,%3};"
        : "+f"(c[0]), "+f"(c[1]), "+f"(c[2]), "+f"(c[3])
        : "r"(a[0]), "r"(a[1]), "r"(a[2]), "r"(a[3]), "r"(b0), "r"(b1));
}
__device__ __forceinline__ uint32_t hfpack(float x, float y) {
    __half2 h = __floats2half2_rn(x, y);
    return *reinterpret_cast<uint32_t*>(&h);
}

__global__ void __launch_bounds__(NT, 1)
sigma_mma_kernel(const float* __restrict__ s,
                 const float* __restrict__ a,
                 const float* __restrict__ W1,
                 const float* __restrict__ b1,
                 const float* __restrict__ W2,
                 const float* __restrict__ b2,
                 float* __restrict__ out) {
    extern __shared__ char smem[];
    uint32_t* W2H32 = (uint32_t*)(smem + OFF_W2H);
    uint32_t* HH32  = (uint32_t*)(smem + OFF_HH);
    float*    sTri  = (float*)(smem + OFF_TRI);
    float*    sX    = (float*)(smem + OFF_X);
    float*    sW1   = (float*)(smem + OFF_W1);
    float*    sB1   = (float*)(smem + OFF_B1);
    float*    sB2   = (float*)(smem + OFF_B2);
    int*      sTbl  = (int*)(smem + OFF_TBL);

    const int tid = threadIdx.x;
    const uint32_t sXaddr = smem_u32p(sX);

    // ================= one-time staging =================
    // W2 [528][64] fp32 -> fp16, row stride 72 halves
    for (int idx = tid; idx < TRI * 32; idx += NT) {
        int t = idx >> 5, kw = idx & 31;
        float2 w = *reinterpret_cast<const float2*>(&W2[t * HID + kw * 2]);
        W2H32[t * WS32 + kw] = hfpack(w.x, w.y);
    }
    for (int idx = tid; idx < (NCOLS - TRI) * WS32; idx += NT) {
        int t = TRI + idx / WS32, kw = idx % WS32;
        W2H32[t * WS32 + kw] = 0u;
    }
    // W1 [64][40] copied as-is (k-major), row pad 44
    for (int idx = tid; idx < HID * 10; idx += NT) {
        int hh = idx / 10, k4 = idx - hh * 10;
        float4 w = *reinterpret_cast<const float4*>(&W1[hh * INDIM + k4 * 4]);
        *reinterpret_cast<float4*>(&sW1[hh * XPAD + k4 * 4]) = w;
    }
    if (tid < HID) sB1[tid] = b1[tid];
    for (int idx = tid; idx < NCOLS; idx += NT)
        sB2[idx] = (idx < TRI) ? b2[idx] : 0.0f;
    for (int o = tid; o < 1024; o += NT) {
        int i = o >> 5, j = o & 31;
        int ii = (i < j) ? i : j;
        int jj = (i < j) ? j : i;
        int t = ii * 32 - ((ii * (ii + 1)) >> 1) + jj;
        sTbl[o] = t | ((i == j) ? (1 << 16) : 0);
    }

    // prefetch X for first tile
    const int tile0 = blockIdx.x;
    {
        int row0 = tile0 * ROWS;
        if (tid < 512) {
            int r = tid >> 3, c4 = tid & 7;
            cp16(sXaddr + (r * XPAD + c4 * 4) * 4, &s[(size_t)(row0 + r) * SDIM + c4 * 4]);
        } else if (tid < 640) {
            int t2 = tid - 512, r2 = t2 >> 1, d4 = t2 & 1;
            cp16(sXaddr + (r2 * XPAD + SDIM + d4 * 4) * 4,
                 &a[(size_t)(row0 + r2) * ADIM + d4 * 4]);
        }
        cp_commit();
    }
    cp_wait0();
    __syncthreads();

    // MMA mapping: 32 warps = 4 M-blocks(16r) x 8 N-blocks(72c = 9 n8-tiles).
    const int wi   = tid >> 5, lane = tid & 31;
    const int rb   = wi >> 3,  cb   = wi & 7;
    const int l4   = lane >> 2, lm  = lane & 3;
    const int wcol = cb * 72;

    const uint32_t hhBase = smem_u32p(HH32);
    const uint32_t w2Base = smem_u32p(W2H32);
    const uint32_t aAddr = hhBase +
        (((rb * 16 + (lane & 15)) * WS32 + ((lane >> 4) << 2)) << 2);
    const uint32_t bAddr = w2Base +
        (((wcol + (lane & 7) + ((lane & 16) >> 1)) * WS32 + (((lane >> 3) & 1) << 2)) << 2);
    const uint32_t b8Addr = w2Base +
        (((wcol + 64 + (lane & 7)) * WS32 + (((lane >> 3) & 1) << 2)) << 2);

    // P1 mapping: 32 warps = 8 row-blocks(8r) x 4 col-blocks(16c);
    // thread: rows r0,r0+1; cols c0,c0+1.
    const int p1r0 = (wi & 7) * 8 + 2 * (lane >> 3);
    const int p1c0 = (wi >> 3) * 16 + 2 * (lane & 7);

    // hoisted scatter constants (tile-invariant)
    const int4 tt = ((const int4*)sTbl)[tid & 255];
    const int to0 = tt.x & 0xffff, to1 = tt.y & 0xffff;
    const int to2 = tt.z & 0xffff, to3 = tt.w & 0xffff;
    const int fl0 = tt.x >> 16, fl1 = tt.y >> 16, fl2 = tt.z >> 16, fl3 = tt.w >> 16;
    const float* const trBase = &sTri[(tid >> 8) * TPAD];
    float* const trW0 = &sTri[l4 * TPAD + wcol + 2 * lm];
    float* const trW1 = trW0 + 8 * TPAD;

    // ================= persistent tile loop =================
    for (int tile = tile0; tile < NTILES; tile += GRID) {
        const int row0 = tile * ROWS;

        // ---- Phase 1: H = relu(X @ W1^T + b1) -> fp16 (broadcast-tiled) ----
        {
            // accs: (even-k partial, odd-k partial) per output
            u64 a00 = pack2(sB1[p1c0], 0.f);
            u64 a01 = pack2(sB1[p1c0 + 1], 0.f);
            u64 a10 = a00, a11 = a01;
            const ulonglong2* xr0 = reinterpret_cast<const ulonglong2*>(&sX[p1r0 * XPAD]);
            const ulonglong2* xr1 = reinterpret_cast<const ulonglong2*>(&sX[(p1r0 + 1) * XPAD]);
            const ulonglong2* wc0 = reinterpret_cast<const ulonglong2*>(&sW1[p1c0 * XPAD]);
            const ulonglong2* wc1 = reinterpret_cast<const ulonglong2*>(&sW1[(p1c0 + 1) * XPAD]);
#pragma unroll
            for (int k4 = 0; k4 < 10; ++k4) {
                const ulonglong2 xa = xr0[k4];
                const ulonglong2 xb = xr1[k4];
                const ulonglong2 wa = wc0[k4];
                const ulonglong2 wb = wc1[k4];
                fma2(a00, xa.x, wa.x); fma2(a00, xa.y, wa.y);
                fma2(a01, xa.x, wb.x); fma2(a01, xa.y, wb.y);
                fma2(a10, xb.x, wa.x); fma2(a10, xb.y, wa.y);
                fma2(a11, xb.x, wb.x); fma2(a11, xb.y, wb.y);
            }
            float e, o;
            unpack2(a00, e, o); const float h00 = fmaxf(e + o, 0.f);
            unpack2(a01, e, o); const float h01 = fmaxf(e + o, 0.f);
            unpack2(a10, e, o); const float h10 = fmaxf(e + o, 0.f);
            unpack2(a11, e, o); const float h11 = fmaxf(e + o, 0.f);
            const int wword = (p1c0 >> 1);
            HH32[p1r0 * WS32 + wword]       = hfpack(h00, h01);
            HH32[(p1r0 + 1) * WS32 + wword] = hfpack(h10, h11);
        }
        __syncthreads();   // H visible; sX free for prefetch

        // ---- prefetch X of next tile ----
        if (tile + GRID < NTILES) {
            int nrow0 = (tile + GRID) * ROWS;
            if (tid < 512) {
                int r = tid >> 3, c4 = tid & 7;
                cp16(sXaddr + (r * XPAD + c4 * 4) * 4,
                     &s[(size_t)(nrow0 + r) * SDIM + c4 * 4]);
            } else if (tid < 640) {
                int t2 = tid - 512, r2 = t2 >> 1, d4 = t2 & 1;
                cp16(sXaddr + (r2 * XPAD + SDIM + d4 * 4) * 4,
                     &a[(size_t)(nrow0 + r2) * ADIM + d4 * 4]);
            }
            cp_commit();
        }

        // ---- Phase 2: tri = H @ W2^T + b2 (HMMA fp16) ----
        float c[9][4];
#pragma unroll
        for (int j = 0; j < 9; ++j) {
            float2 bb = *reinterpret_cast<const float2*>(&sB2[wcol + j * 8 + 2 * lm]);
            c[j][0] = bb.x; c[j][1] = bb.y;
            c[j][2] = bb.x; c[j][3] = bb.y;
        }
#pragma unroll
        for (int kk = 0; kk < 4; ++kk) {
            const uint32_t kb = kk * 32;
            uint32_t ah[4];
            ldsm4(ah, aAddr + kb);
#pragma unroll
            for (int p = 0; p < 4; ++p) {
                uint32_t bh[4];
                ldsm4(bh, bAddr + p * 2304 + kb);
                mma_f16(c[2 * p],     ah, bh[0], bh[1]);
                mma_f16(c[2 * p + 1], ah, bh[2], bh[3]);
            }
            {
                uint32_t bh[2];
                ldsm2(bh, b8Addr + kb);
                mma_f16(c[8], ah, bh[0], bh[1]);
            }
        }

        // ---- Phase 3: 4 stages of 16 rows via smem chunk + table scatter ----
#pragma unroll
        for (int st = 0; st < 4; ++st) {
            if (rb == st) {
#pragma unroll
                for (int j = 0; j < 9; ++j) {
                    *reinterpret_cast<float2*>(trW0 + j * 8) = make_float2(c[j][0], c[j][1]);
                    *reinterpret_cast<float2*>(trW1 + j * 8) = make_float2(c[j][2], c[j][3]);
                }
            }
            __syncthreads();

            float4* out4 = reinterpret_cast<float4*>(out + (size_t)(row0 + st * 16) * 1024);
#pragma unroll
            for (int it = 0; it < 4; ++it) {
                const float* tr = trBase + it * 4 * TPAD;
                float v0 = tr[to0], v1 = tr[to1], v2 = tr[to2], v3 = tr[to3];
                if (fl0) v0 = __expf(v0);
                if (fl1) v1 = __expf(v1);
                if (fl2) v2 = __expf(v2);
                if (fl3) v3 = __expf(v3);
                out4[tid + it * NT] = make_float4(v0, v1, v2, v3);
            }
            if (st == 3) cp_wait0();
            __syncthreads();
        }
    }
}

extern "C" void kernel_launch(void* const* d_in, const int* in_sizes, int n_in,
                              void* d_out, int out_size) {
    (void)in_sizes; (void)n_in; (void)out_size;
    const float* s  = (const float*)d_in[0];
    const float* a  = (const float*)d_in[1];
    const float* W1 = (const float*)d_in[2];
    const float* b1 = (const float*)d_in[3];
    const float* W2 = (const float*)d_in[4];
    const float* b2 = (const float*)d_in[5];
    float* out = (float*)d_out;

    cudaFuncSetAttribute(sigma_mma_kernel,
                         cudaFuncAttributeMaxDynamicSharedMemorySize, SMEM_BYTES);
    sigma_mma_kernel<<<GRID, NT, SMEM_BYTES>>>(s, a, W1, b1, W2, b2, out);
}